// round 14
// baseline (speedup 1.0000x reference)
#include <cuda_runtime.h>
#include <math.h>

#define BB 64
#define NN 16800
#define CC 21
#define TPB 256
#define NBLK 66          // ceil(16800/256)
#define FP32_EPS 1.1920928955078125e-07f
#define FBINS 512        // linear bins, width 1/32 over [0,16)

// ---------------- scratch (device globals; no allocation) ----------------
__device__ float    d_psl1[BB * NBLK];
__device__ float    d_pce [BB * NBLK];
__device__ int      d_ppos[BB * NBLK];
__device__ unsigned d_gcnt[BB * FBINS];   // zero-init; k_fin re-zeros (replay-invariant)
__device__ float    d_gsum[BB * FBINS];   // zero-init; k_fin re-zeros
__device__ float    d_res [BB * 3];
__device__ int      d_done;               // ticket (self-resetting)

__device__ __forceinline__ float smooth_l1(float d) {
    float a = fabsf(d);
    return (a < 1.f) ? (0.5f * a * a) : (a - 0.5f);
}

// linear equal-width bin over [0,16), width 1/32
__device__ __forceinline__ unsigned fbin(float v) {
    return min((unsigned)(FBINS - 1), (unsigned)(v * 32.0f));
}

// gpu-scope acq_rel fetch-add (orders prior stores w/o MEMBAR.GL/CCTL.IVALL)
__device__ __forceinline__ int atom_add_acqrel(int* p, int v) {
    int old;
    asm volatile("atom.global.acq_rel.gpu.add.s32 %0, [%1], %2;"
                 : "=r"(old) : "l"(p), "r"(v) : "memory");
    return old;
}

// ---------------- main: sl1 + ce + partials + fused 512-bin histogram ----------------
__global__ void __launch_bounds__(TPB, 8)
k_main(const float4* __restrict__ pb,
       const float4* __restrict__ gb,
       const float4* __restrict__ pl4,
       const int*    __restrict__ gl,
       const float4* __restrict__ anc)
{
    // s_mem reuse: (1) p_labels staging 21504 B; (2) hist cnt[512]+sum[512] = 4 KB
    __shared__ __align__(16) char s_mem[TPB * CC * 4];
    __shared__ float rs[8], rc[8];
    __shared__ int   rp[8];

    const int b    = blockIdx.y;
    const int base = blockIdx.x * TPB;
    const int tid  = threadIdx.x;
    const int lane = tid & 31;
    const int w    = tid >> 5;
    const int n    = base + tid;
    const int cnt  = min(TPB, NN - base);

    float* s_lab = (float*)s_mem;

    // hoisted loads: issue before staging so latency overlaps the staging phase
    float4 a = make_float4(1.f, 1.f, 1.f, 1.f);
    float4 g = make_float4(1.f, 1.f, 1.f, 1.f);
    float4 p = make_float4(0.f, 0.f, 0.f, 0.f);
    int lab = 0;
    if (tid < cnt) {
        a   = anc[n];
        g   = gb[b * NN + n];
        p   = pb[b * NN + n];
        lab = gl[b * NN + n];
    }

    // stage p_labels chunk (float4 coalesced, fully unrolled: 1344 float4 / 256 thr)
    {
        const float4* src = pl4 + ((size_t)b * NN + base) * CC / 4;
        float4* dst = (float4*)s_lab;
        const int tot4 = (cnt * CC) >> 2;
        #pragma unroll 6
        for (int i = tid; i < tot4; i += TPB) dst[i] = src[i];
    }
    __syncthreads();

    float sl1 = 0.f, ce = 0.f;
    int pos = 0;
    if (tid < cnt) {
        float t0 = 10.f * (g.x - a.x) / a.z;
        float t1 = 10.f * (g.y - a.y) / a.w;
        float t2 = 5.f * __logf(g.z / a.z);
        float t3 = 5.f * __logf(g.w / a.w);
        sl1 = smooth_l1(p.x - t0) + smooth_l1(p.y - t1)
            + smooth_l1(p.z - t2) + smooth_l1(p.w - t3);

        const float* x = s_lab + tid * CC;   // stride 21, conflict-free
        float s = 0.f;
        #pragma unroll
        for (int j = 0; j < CC; j++) s += __expf(x[j]);
        ce = __logf(s) - x[lab];
        pos = (lab > 0);
    }
    const float negv = pos ? 0.f : fmaxf(ce, 0.f);

    // per-block partials (positives)
    {
        float vsl = pos ? sl1 : 0.f;
        float vce = pos ? ce  : 0.f;
        #pragma unroll
        for (int o = 16; o; o >>= 1) {
            vsl += __shfl_down_sync(0xFFFFFFFFu, vsl, o);
            vce += __shfl_down_sync(0xFFFFFFFFu, vce, o);
        }
        int wp = __popc(__ballot_sync(0xFFFFFFFFu, pos));
        if (lane == 0) { rs[w] = vsl; rc[w] = vce; rp[w] = wp; }
    }
    __syncthreads();   // partials visible; s_lab reads done -> s_mem reusable
    if (tid == 0) {
        float A = 0.f, Cc = 0.f; int P = 0;
        #pragma unroll
        for (int i = 0; i < 8; i++) { A += rs[i]; Cc += rc[i]; P += rp[i]; }
        const int idx = b * NBLK + blockIdx.x;
        d_psl1[idx] = A;
        d_pce [idx] = Cc;
        d_ppos[idx] = P;
    }

    // ---- block-local 512-bin histogram ----
    unsigned* hc = (unsigned*)s_mem;          // 512 u32
    float*    hf = (float*)(hc + FBINS);      // 512 f32
    for (int i = tid; i < FBINS; i += TPB) { hc[i] = 0u; hf[i] = 0.f; }
    __syncthreads();
    if (tid < cnt) {
        unsigned bin = fbin(negv);
        atomicAdd(&hc[bin], 1u);
        atomicAdd(&hf[bin], negv);
    }
    __syncthreads();
    // merge populated bins to per-batch global hist (spread REDG)
    for (int i = tid; i < FBINS; i += TPB) {
        unsigned c = hc[i];
        if (c) {
            atomicAdd(&d_gcnt[b * FBINS + i], c);
            atomicAdd(&d_gsum[b * FBINS + i], hf[i]);
        }
    }
}

// ---------------- fin: ONE WARP per batch; no barriers, no fences ----------------
__global__ void __launch_bounds__(32)
k_fin(float* __restrict__ out)
{
    const int b    = blockIdx.x;
    const int lane = threadIdx.x;

    // lane owns 16 consecutive bins; load + zero for replay
    unsigned c16[16]; float f16[16];
    unsigned ct = 0; float ft = 0.f;
    {
        const int gbase = b * FBINS + lane * 16;
        #pragma unroll
        for (int j = 0; j < 16; j++) {
            c16[j] = d_gcnt[gbase + j];
            f16[j] = d_gsum[gbase + j];
            ct += c16[j]; ft += f16[j];
            d_gcnt[gbase + j] = 0u;
            d_gsum[gbase + j] = 0.f;
        }
    }

    // partials reduce (66 entries, 3 per lane)
    float A, Cc; int P;
    {
        const int idx = b * NBLK + lane;
        A  = d_psl1[idx] + d_psl1[idx + 32] + ((lane < 2) ? d_psl1[idx + 64] : 0.f);
        Cc = d_pce [idx] + d_pce [idx + 32] + ((lane < 2) ? d_pce [idx + 64] : 0.f);
        P  = d_ppos[idx] + d_ppos[idx + 32] + ((lane < 2) ? d_ppos[idx + 64] : 0);
        #pragma unroll
        for (int o = 16; o; o >>= 1) {
            A  += __shfl_down_sync(0xFFFFFFFFu, A, o);
            Cc += __shfl_down_sync(0xFFFFFFFFu, Cc, o);
            P  += __shfl_down_sync(0xFFFFFFFFu, P, o);
        }
        A  = __shfl_sync(0xFFFFFFFFu, A, 0);
        Cc = __shfl_sync(0xFFFFFFFFu, Cc, 0);
        P  = __shfl_sync(0xFFFFFFFFu, P, 0);
    }
    const int posn = P;
    const int k0   = min(3 * posn, NN);

    // inclusive suffix over lanes (higher lane = higher bins)
    unsigned sc_ = ct; float sf_ = ft;
    #pragma unroll
    for (int o = 1; o < 32; o <<= 1) {
        unsigned vc = __shfl_down_sync(0xFFFFFFFFu, sc_, o);
        float    vf = __shfl_down_sync(0xFFFFFFFFu, sf_, o);
        if (lane + o < 32) { sc_ += vc; sf_ += vf; }
    }

    float negloc = 0.f;
    if (k0 > 0) {
        const unsigned above_c = sc_ - ct;
        const float    above_f = sf_ - ft;
        if (above_c < (unsigned)k0 && above_c + ct >= (unsigned)k0) {
            // exactly one lane: walk own 16 bins high->low; mean closure at boundary
            unsigned cum = above_c; float fa = above_f;
            #pragma unroll
            for (int j = 15; j >= 0; j--) {
                unsigned h = c16[j];
                if (cum + h >= (unsigned)k0) {
                    const float mean = f16[j] / (float)h;
                    negloc = fa + (float)(k0 - (int)cum) * mean;
                    break;
                }
                cum += h; fa += f16[j];
            }
        }
    }
    // exactly one lane holds negloc != contribution; warp-sum broadcasts it
    #pragma unroll
    for (int o = 16; o; o >>= 1) negloc += __shfl_down_sync(0xFFFFFFFFu, negloc, o);
    const float negsum = __shfl_sync(0xFFFFFFFFu, negloc, 0);

    int is_last = 0;
    if (lane == 0) {
        float lb = A;
        float ll = Cc + negsum;
        float nm = (posn > 0) ? 1.f : 0.f;
        float pf = fmaxf((float)posn, FP32_EPS);
        d_res[b * 3 + 0] = (lb + ll) * nm / pf;
        d_res[b * 3 + 1] = lb * nm / pf;
        d_res[b * 3 + 2] = ll * nm / pf;
        // acq_rel ticket: orders the d_res stores, acquires others' stores
        is_last = (atom_add_acqrel(&d_done, 1) == BB - 1);
    }
    is_last = __shfl_sync(0xFFFFFFFFu, is_last, 0);

    // cross-batch final reduction (last warp to finish); volatile reads (L2)
    if (is_last) {
        volatile float* r = d_res;
        float lt = r[lane * 3 + 0]           + r[(lane + 32) * 3 + 0];
        float vb = r[lane * 3 + 1]           + r[(lane + 32) * 3 + 1];
        float vl = r[lane * 3 + 2]           + r[(lane + 32) * 3 + 2];
        #pragma unroll
        for (int o = 16; o; o >>= 1) {
            lt += __shfl_down_sync(0xFFFFFFFFu, lt, o);
            vb += __shfl_down_sync(0xFFFFFFFFu, vb, o);
            vl += __shfl_down_sync(0xFFFFFFFFu, vl, o);
        }
        if (lane == 0) {
            out[0] = lt * (1.f / 64.f);
            out[1] = vb * (1.f / 64.f);
            out[2] = vl * (1.f / 64.f);
            d_done = 0;   // self-reset for next graph replay
        }
    }
}

// ---------------- launch ----------------
extern "C" void kernel_launch(void* const* d_in, const int* in_sizes, int n_in,
                              void* d_out, int out_size) {
    const float4* pb  = (const float4*)d_in[0];
    const float4* gb  = (const float4*)d_in[1];
    const float4* pl4 = (const float4*)d_in[2];
    const int*    gl  = (const int*)d_in[3];
    const float4* anc = (const float4*)d_in[4];
    float* out = (float*)d_out;

    dim3 gBN(NBLK, BB);
    k_main<<<gBN, TPB>>>(pb, gb, pl4, gl, anc);
    k_fin<<<BB, 32>>>(out);
}

// round 15
// speedup vs baseline: 1.5519x; 1.5519x over previous
#include <cuda_runtime.h>
#include <math.h>

#define BB 64
#define NN 16800
#define CC 21
#define TPB 256
#define NBLK 66          // ceil(16800/256)
#define FP32_EPS 1.1920928955078125e-07f
#define FBINS 512        // linear bins, width 1/32 over [0,16)

// ---------------- scratch (device globals; no allocation) ----------------
__device__ float    d_psl1[BB * NBLK];
__device__ float    d_pce [BB * NBLK];
__device__ int      d_ppos[BB * NBLK];
__device__ unsigned d_gcnt[BB * FBINS];   // zero-init; k_fin re-zeros (replay-invariant)
__device__ float    d_gsum[BB * FBINS];   // zero-init; k_fin re-zeros
__device__ float    d_res [BB * 3];
__device__ int      d_done;               // ticket (self-resetting)

__device__ __forceinline__ float smooth_l1(float d) {
    float a = fabsf(d);
    return (a < 1.f) ? (0.5f * a * a) : (a - 0.5f);
}

// linear equal-width bin over [0,16), width 1/32
__device__ __forceinline__ unsigned fbin(float v) {
    return min((unsigned)(FBINS - 1), (unsigned)(v * 32.0f));
}

// ---------------- main: sl1 + ce + partials + fused 512-bin histogram ----------------
// (byte-identical to R13 -- proven 29.2 us)
__global__ void __launch_bounds__(TPB, 8)
k_main(const float4* __restrict__ pb,
       const float4* __restrict__ gb,
       const float4* __restrict__ pl4,
       const int*    __restrict__ gl,
       const float4* __restrict__ anc)
{
    __shared__ __align__(16) char s_mem[TPB * CC * 4];
    __shared__ float rs[8], rc[8];
    __shared__ int   rp[8];

    const int b    = blockIdx.y;
    const int base = blockIdx.x * TPB;
    const int tid  = threadIdx.x;
    const int lane = tid & 31;
    const int w    = tid >> 5;
    const int n    = base + tid;
    const int cnt  = min(TPB, NN - base);

    float* s_lab = (float*)s_mem;

    {
        const float4* src = pl4 + ((size_t)b * NN + base) * CC / 4;
        float4* dst = (float4*)s_lab;
        const int tot4 = (cnt * CC) >> 2;
        for (int i = tid; i < tot4; i += TPB) dst[i] = src[i];
    }
    __syncthreads();

    float sl1 = 0.f, ce = 0.f;
    int pos = 0;
    if (tid < cnt) {
        float4 a = anc[n];
        float4 g = gb[b * NN + n];
        float4 p = pb[b * NN + n];
        float t0 = 10.f * (g.x - a.x) / a.z;
        float t1 = 10.f * (g.y - a.y) / a.w;
        float t2 = 5.f * __logf(g.z / a.z);
        float t3 = 5.f * __logf(g.w / a.w);
        sl1 = smooth_l1(p.x - t0) + smooth_l1(p.y - t1)
            + smooth_l1(p.z - t2) + smooth_l1(p.w - t3);

        const float* x = s_lab + tid * CC;   // stride 21, conflict-free
        float s = 0.f;
        #pragma unroll
        for (int j = 0; j < CC; j++) s += __expf(x[j]);
        int lab = gl[b * NN + n];
        ce = __logf(s) - x[lab];
        pos = (lab > 0);
    }
    const float negv = pos ? 0.f : fmaxf(ce, 0.f);

    {
        float vsl = pos ? sl1 : 0.f;
        float vce = pos ? ce  : 0.f;
        #pragma unroll
        for (int o = 16; o; o >>= 1) {
            vsl += __shfl_down_sync(0xFFFFFFFFu, vsl, o);
            vce += __shfl_down_sync(0xFFFFFFFFu, vce, o);
        }
        int wp = __popc(__ballot_sync(0xFFFFFFFFu, pos));
        if (lane == 0) { rs[w] = vsl; rc[w] = vce; rp[w] = wp; }
    }
    __syncthreads();
    if (tid == 0) {
        float A = 0.f, Cc = 0.f; int P = 0;
        #pragma unroll
        for (int i = 0; i < 8; i++) { A += rs[i]; Cc += rc[i]; P += rp[i]; }
        const int idx = b * NBLK + blockIdx.x;
        d_psl1[idx] = A;
        d_pce [idx] = Cc;
        d_ppos[idx] = P;
    }

    unsigned* hc = (unsigned*)s_mem;          // 512 u32
    float*    hf = (float*)(hc + FBINS);      // 512 f32
    for (int i = tid; i < FBINS; i += TPB) { hc[i] = 0u; hf[i] = 0.f; }
    __syncthreads();
    if (tid < cnt) {
        unsigned bin = fbin(negv);
        atomicAdd(&hc[bin], 1u);
        atomicAdd(&hf[bin], negv);
    }
    __syncthreads();
    for (int i = tid; i < FBINS; i += TPB) {
        unsigned c = hc[i];
        if (c) {
            atomicAdd(&d_gcnt[b * FBINS + i], c);
            atomicAdd(&d_gsum[b * FBINS + i], hf[i]);
        }
    }
}

// ---------------- fin: one block per batch (R13-proven) + PDL early start ----------------
__global__ void __launch_bounds__(TPB)
k_fin(float* __restrict__ out)
{
    const int b    = blockIdx.x;
    const int tid  = threadIdx.x;
    const int lane = tid & 31;
    const int w    = tid >> 5;

    // PDL: block is resident early; wait here until k_main's grid completes.
#if __CUDA_ARCH__ >= 900
    cudaGridDependencySynchronize();
#endif

    __shared__ float a66[NBLK], c66[NBLK];
    __shared__ int   p66[NBLK];
    __shared__ unsigned s_wc[8];
    __shared__ float    s_wf[8];
    __shared__ float red[8];
    __shared__ float sA, sC, s_negsum;
    __shared__ int   sP, s_lastg;

    // thread owns 2 consecutive bins; load (L2) + zero for replay
    unsigned c2[2]; float f2[2];
    {
        const int gbase = b * FBINS + tid * 2;
        #pragma unroll
        for (int j = 0; j < 2; j++) {
            c2[j] = d_gcnt[gbase + j];
            f2[j] = d_gsum[gbase + j];
            d_gcnt[gbase + j] = 0u;
            d_gsum[gbase + j] = 0.f;
        }
    }
    if (tid < NBLK) {
        const int idx = b * NBLK + tid;
        a66[tid] = d_psl1[idx];
        c66[tid] = d_pce [idx];
        p66[tid] = d_ppos[idx];
    }
    if (tid == 0) s_negsum = 0.f;
    __syncthreads();

    // reduce partials (warp 0)
    if (tid < 32) {
        float A  = a66[tid] + a66[tid + 32] + ((tid < 2) ? a66[tid + 64] : 0.f);
        float Cc = c66[tid] + c66[tid + 32] + ((tid < 2) ? c66[tid + 64] : 0.f);
        int   P  = p66[tid] + p66[tid + 32] + ((tid < 2) ? p66[tid + 64] : 0);
        #pragma unroll
        for (int o = 16; o; o >>= 1) {
            A  += __shfl_down_sync(0xFFFFFFFFu, A, o);
            Cc += __shfl_down_sync(0xFFFFFFFFu, Cc, o);
            P  += __shfl_down_sync(0xFFFFFFFFu, P, o);
        }
        if (tid == 0) { sA = A; sC = Cc; sP = P; }
    }

    // per-warp inclusive suffix over lanes (higher lane = higher bins)
    const unsigned ct = c2[0] + c2[1];
    const float    ft = f2[0] + f2[1];
    unsigned sc_ = ct; float sf_ = ft;
    #pragma unroll
    for (int o = 1; o < 32; o <<= 1) {
        unsigned vc = __shfl_down_sync(0xFFFFFFFFu, sc_, o);
        float    vf = __shfl_down_sync(0xFFFFFFFFu, sf_, o);
        if (lane + o < 32) { sc_ += vc; sf_ += vf; }
    }
    if (lane == 0) { s_wc[w] = sc_; s_wf[w] = sf_; }
    __syncthreads();

    const int posn = sP;
    const int k0   = min(3 * posn, NN);

    if (k0 > 0) {
        unsigned awc = 0; float awf = 0.f;
        #pragma unroll
        for (int j = 0; j < 8; j++) if (j > w) { awc += s_wc[j]; awf += s_wf[j]; }
        const unsigned above_c = awc + (sc_ - ct);
        const float    above_f = awf + (sf_ - ft);

        if (above_c < (unsigned)k0 && above_c + ct >= (unsigned)k0) {
            unsigned cum = above_c; float fa = above_f;
            #pragma unroll
            for (int j = 1; j >= 0; j--) {
                unsigned h = c2[j];
                if (cum + h >= (unsigned)k0) {
                    const float mean = f2[j] / (float)h;
                    s_negsum = fa + (float)(k0 - (int)cum) * mean;
                    break;
                }
                cum += h; fa += f2[j];
            }
        }
    }
    __syncthreads();

    if (tid == 0) {
        float lb = sA;
        float ll = sC + s_negsum;
        float nm = (posn > 0) ? 1.f : 0.f;
        float pf = fmaxf((float)posn, FP32_EPS);
        d_res[b * 3 + 0] = (lb + ll) * nm / pf;
        d_res[b * 3 + 1] = lb * nm / pf;
        d_res[b * 3 + 2] = ll * nm / pf;
        __threadfence();
        s_lastg = (atomicAdd(&d_done, 1) == BB - 1);
    }
    __syncthreads();

    if (s_lastg) {
        __threadfence();
        float lt = 0.f, vb = 0.f, vl = 0.f;
        if (tid < BB) {
            volatile float* r = d_res;
            lt = r[tid * 3 + 0];
            vb = r[tid * 3 + 1];
            vl = r[tid * 3 + 2];
        }
        if (tid < 64) {
            #pragma unroll
            for (int o = 16; o; o >>= 1) {
                lt += __shfl_down_sync(0xFFFFFFFFu, lt, o);
                vb += __shfl_down_sync(0xFFFFFFFFu, vb, o);
                vl += __shfl_down_sync(0xFFFFFFFFu, vl, o);
            }
            if ((tid & 31) == 0) {
                red[tid >> 5]       = lt;
                red[(tid >> 5) + 2] = vb;
                red[(tid >> 5) + 4] = vl;
            }
        }
        __syncthreads();
        if (tid == 0) {
            out[0] = (red[0] + red[1]) * (1.f / 64.f);
            out[1] = (red[2] + red[3]) * (1.f / 64.f);
            out[2] = (red[4] + red[5]) * (1.f / 64.f);
            d_done = 0;   // self-reset for next graph replay
        }
    }
}

// ---------------- launch ----------------
extern "C" void kernel_launch(void* const* d_in, const int* in_sizes, int n_in,
                              void* d_out, int out_size) {
    const float4* pb  = (const float4*)d_in[0];
    const float4* gb  = (const float4*)d_in[1];
    const float4* pl4 = (const float4*)d_in[2];
    const int*    gl  = (const int*)d_in[3];
    const float4* anc = (const float4*)d_in[4];
    float* out = (float*)d_out;

    dim3 gBN(NBLK, BB);
    k_main<<<gBN, TPB>>>(pb, gb, pl4, gl, anc);

    // PDL launch for k_fin: starts (and schedules) while k_main drains;
    // cudaGridDependencySynchronize() inside gates the data reads.
    cudaLaunchConfig_t cfg = {};
    cfg.gridDim  = dim3(BB, 1, 1);
    cfg.blockDim = dim3(TPB, 1, 1);
    cudaLaunchAttribute attr[1];
    attr[0].id = cudaLaunchAttributeProgrammaticStreamSerialization;
    attr[0].val.programmaticStreamSerializationAllowed = 1;
    cfg.attrs = attr;
    cfg.numAttrs = 1;
    cudaLaunchKernelEx(&cfg, k_fin, out);
}